// round 15
// baseline (speedup 1.0000x reference)
#include <cuda_runtime.h>

// QHadamard: y = FWHT_4096(x) / 64, rows = 8192, DIM = 4096.
// R15: vectorized-GMEM variant of the converged 3-pass / 2-transpose design.
// Bit assignment (element index e[11:0]):
//   A: transforms {0,1,7,8,9}: 8x LDG.128 (comp=e{0,1}, reg=e{7,8,9},
//      lane=e{2..6}, warp=e{10,11}), 8x STS.128.
//   B: transforms {2..6}: scalar smem in-place (the one forced-scalar pass).
//   C: transforms {10,11}: 8x LDS.128 (reg=e{9,10,11}), 8x STG.128 dense.
// Unified swizzle phys_word(a) = a ^ (((a>>7)&7)<<2)  [f4: q ^ ((q>>5)&7)]
// -- verified conflict-free in all five smem phases.
// A->B exchange intra-warp (B warp bits = e{10,11} = A warp) -> __syncwarp;
// B in-place region is warp-private; B->C spans warps -> __syncthreads.
// Same instruction count & L1-wavefront floor (192/warp) as R4/R11, but GMEM
// reads issue as 8 x 512B requests instead of 32 x 128B.

#define DIM 4096
#define THREADS 128

__device__ __forceinline__ void bfly(float& a, float& b) {
    float t = a; a = t + b; b = t - b;
}

__device__ __forceinline__ void fwht32(float* x) {
#pragma unroll
    for (int h = 1; h < 32; h <<= 1)
#pragma unroll
        for (int i = 0; i < 32; i += (h << 1))
#pragma unroll
            for (int j = i; j < i + h; ++j) bfly(x[j], x[j + h]);
}

__global__ void __launch_bounds__(THREADS, 8)
QHadamard_24524263260380_kernel(const float* __restrict__ in,
                                float* __restrict__ out) {
    __shared__ float s[DIM];                       // 16 KB, swizzled layout

    const int    T   = threadIdx.x;                // 0..127
    const size_t row = (size_t)blockIdx.x * DIM;
    const int    L   = T & 31;                     // e{2..6}
    const int    W   = T >> 5;                     // e{10,11}

    // ---- Pass A: 8x LDG.128; x[r*4+c]: c=e{0,1}, r=e{7,8,9} ----
    const float4* g4 = reinterpret_cast<const float4*>(in + row);
    const int qa = L + (W << 8);                   // f4 idx base; + r*32
    float x[32];
#pragma unroll
    for (int r = 0; r < 8; ++r) {
        float4 v = g4[qa + (r << 5)];
        x[r*4+0] = v.x; x[r*4+1] = v.y; x[r*4+2] = v.z; x[r*4+3] = v.w;
    }
    const float scale = 0.015625f;                 // 1/sqrt(4096)
#pragma unroll
    for (int k = 0; k < 32; ++k) x[k] *= scale;

    fwht32(x);                                     // FWHT over e{0,1,7,8,9}

    // ---- T1: 8x STS.128 at phys_f4 = q ^ ((q>>5)&7); here (q>>5)&7 = r ----
    float4* s4 = reinterpret_cast<float4*>(s);
#pragma unroll
    for (int r = 0; r < 8; ++r) {
        s4[(qa + (r << 5)) ^ r] =
            make_float4(x[r*4+0], x[r*4+1], x[r*4+2], x[r*4+3]);
    }
    // A->B exchange is intra-warp (both keyed by e{10,11}): warp sync suffices.
    __syncwarp(0xffffffffu);

    // ---- Pass B: scalar, thread bits (e0,e1,e7,e8,e9,e10,e11); m = e{2..6}.
    //      word addr a(m) = (T&3) + 4m + 128*(T>>2); swizzle XOR = e{7,8,9}<<2.
    //      Banks (l&3) + 4*((m&7)^(l>>2)) -> 32 distinct per instruction. ----
    const int bbase = (T & 3) + ((T >> 2) << 7);   // + 4m
    const int bx    = ((T >> 2) & 7) << 2;
    float y[32];
#pragma unroll
    for (int m = 0; m < 32; ++m) y[m] = s[(bbase + (m << 2)) ^ bx];

    fwht32(y);                                     // FWHT over e{2..6}

#pragma unroll
    for (int m = 0; m < 32; ++m) s[(bbase + (m << 2)) ^ bx] = y[m];
    __syncthreads();                               // B->C spans all warps

    // ---- Pass C: q = T + 128r (lane=e{2..6}, warp=e{7,8}, r=e{9,10,11});
    //      phys_f4 = q ^ ((T>>5) + 4*(r&1)). z[r*4+c]: z bits {3,4} = e{10,11}.
    float z[32];
#pragma unroll
    for (int r = 0; r < 8; ++r) {
        const int px = (T >> 5) + ((r & 1) << 2);
        float4 v = s4[(T + (r << 7)) ^ px];
        z[r*4+0] = v.x; z[r*4+1] = v.y; z[r*4+2] = v.z; z[r*4+3] = v.w;
    }
    // FWHT over e{10,11} = z-index bits {3,4}
#pragma unroll
    for (int hi = 0; hi < 32; hi += 16)
#pragma unroll
        for (int j = 0; j < 8; ++j) bfly(z[hi + j], z[hi + j + 8]);
#pragma unroll
    for (int j = 0; j < 16; ++j) bfly(z[j], z[j + 16]);

    // ---- 8x STG.128, dense: per instruction 32 consecutive float4 ----
    float4* o4 = reinterpret_cast<float4*>(out + row);
#pragma unroll
    for (int r = 0; r < 8; ++r) {
        o4[T + (r << 7)] =
            make_float4(z[r*4+0], z[r*4+1], z[r*4+2], z[r*4+3]);
    }
}

extern "C" void kernel_launch(void* const* d_in, const int* in_sizes, int n_in,
                              void* d_out, int out_size) {
    const float* x   = (const float*)d_in[0];
    float*       out = (float*)d_out;
    const int rows = in_sizes[0] / DIM;             // 8192
    QHadamard_24524263260380_kernel<<<rows, THREADS>>>(x, out);
}

// round 16
// speedup vs baseline: 1.0021x; 1.0021x over previous
#include <cuda_runtime.h>

// QHadamard: y = FWHT_4096(x) / 64, rows = 8192, DIM = 4096.
// R16: R15's vectorized 3-pass / 2-transpose design with the XOR smem swizzle
// replaced by PADDING: phys(a) = a + 4*(a>>7)  (4 pad words per 128-word
// segment; 16.5 KB). All accesses become [base + immediate] (no per-access
// XOR/IMAD), and every phase stays bank-conflict-free:
//   T1 STS.128 / C LDS.128: words 4*lane + const  -> 32 banks
//   B scalar: bank = (l&3) + 4*((m + (l>>2)) & 7) -> 32 banks (132 = 4 mod 32)
// Bit assignment (element e[11:0]):
//   A: transforms {0,1,7,8,9}: 8x LDG.128 (c=e{0,1}, r=e{7,8,9}, lane=e{2..6},
//      warp=e{10,11}), 8x STS.128 at baseA + 132r words.
//   B: transforms {2..6}: scalar smem in-place at baseB + 4m words.
//   C: transforms {10,11}: 8x LDS.128 at baseC + 528r words; 8x STG.128 dense.
// A->B intra-warp (B warp bits = e{10,11} = A warp) -> __syncwarp;
// B->C spans warps -> __syncthreads.

#define DIM 4096
#define THREADS 128
#define SPAD 4224                              // 4096 + 4*32 pad words

__device__ __forceinline__ void bfly(float& a, float& b) {
    float t = a; a = t + b; b = t - b;
}

__device__ __forceinline__ void fwht32(float* x) {
#pragma unroll
    for (int h = 1; h < 32; h <<= 1)
#pragma unroll
        for (int i = 0; i < 32; i += (h << 1))
#pragma unroll
            for (int j = i; j < i + h; ++j) bfly(x[j], x[j + h]);
}

__global__ void __launch_bounds__(THREADS, 8)
QHadamard_24524263260380_kernel(const float* __restrict__ in,
                                float* __restrict__ out) {
    __shared__ float s[SPAD];                   // 16.5 KB, padded layout

    const int    T   = threadIdx.x;             // 0..127
    const size_t row = (size_t)blockIdx.x * DIM;
    const int    L   = T & 31;                  // e{2..6}
    const int    W   = T >> 5;                  // e{10,11}

    // ---- Pass A: 8x LDG.128; x[r*4+c]: c=e{0,1}, r=e{7,8,9} ----
    const float4* g4 = reinterpret_cast<const float4*>(in + row);
    const int qa = L + (W << 8);                // f4 index base; + r*32
    float x[32];
#pragma unroll
    for (int r = 0; r < 8; ++r) {
        float4 v = g4[qa + (r << 5)];
        x[r*4+0] = v.x; x[r*4+1] = v.y; x[r*4+2] = v.z; x[r*4+3] = v.w;
    }
    const float scale = 0.015625f;              // 1/sqrt(4096)
#pragma unroll
    for (int k = 0; k < 32; ++k) x[k] *= scale;

    fwht32(x);                                  // FWHT over e{0,1,7,8,9}

    // ---- T1: 8x STS.128 at word baseA + 132r  (baseA = 4L + 1056W) ----
    {
        float* sA = s + (L << 2) + W * 1056;
#pragma unroll
        for (int r = 0; r < 8; ++r) {
            *reinterpret_cast<float4*>(sA + r * 132) =
                make_float4(x[r*4+0], x[r*4+1], x[r*4+2], x[r*4+3]);
        }
    }
    // A->B exchange is intra-warp: warp-local sync suffices.
    __syncwarp(0xffffffffu);

    // ---- Pass B: scalar in-place; thread owns e{0,1}=T&3, e{7..11}=T>>2;
    //      m = e{2..6}; word = baseB + 4m  (baseB = (T&3) + 132*(T>>2)) ----
    {
        float* sB = s + (T & 3) + (T >> 2) * 132;
        float y[32];
#pragma unroll
        for (int m = 0; m < 32; ++m) y[m] = sB[m << 2];

        fwht32(y);                              // FWHT over e{2..6}

#pragma unroll
        for (int m = 0; m < 32; ++m) sB[m << 2] = y[m];
    }
    __syncthreads();                            // B->C spans all warps

    // ---- Pass C: lane=e{2..6}=T&31, w=e{7,8}=T>>5, r=e{9,10,11};
    //      word = baseC + 528r  (baseC = 4T + 4w) ----
    float z[32];
    {
        const float* sC = s + (T << 2) + ((T >> 5) << 2);
#pragma unroll
        for (int r = 0; r < 8; ++r) {
            float4 v = *reinterpret_cast<const float4*>(sC + r * 528);
            z[r*4+0] = v.x; z[r*4+1] = v.y; z[r*4+2] = v.z; z[r*4+3] = v.w;
        }
    }
    // FWHT over e{10,11} = z-index bits {3,4}
#pragma unroll
    for (int hi = 0; hi < 32; hi += 16)
#pragma unroll
        for (int j = 0; j < 8; ++j) bfly(z[hi + j], z[hi + j + 8]);
#pragma unroll
    for (int j = 0; j < 16; ++j) bfly(z[j], z[j + 16]);

    // ---- 8x STG.128, dense: per instruction 32 consecutive float4 ----
    float4* o4 = reinterpret_cast<float4*>(out + row);
#pragma unroll
    for (int r = 0; r < 8; ++r) {
        o4[T + (r << 7)] =
            make_float4(z[r*4+0], z[r*4+1], z[r*4+2], z[r*4+3]);
    }
}

extern "C" void kernel_launch(void* const* d_in, const int* in_sizes, int n_in,
                              void* d_out, int out_size) {
    const float* x   = (const float*)d_in[0];
    float*       out = (float*)d_out;
    const int rows = in_sizes[0] / DIM;          // 8192
    QHadamard_24524263260380_kernel<<<rows, THREADS>>>(x, out);
}

// round 17
// speedup vs baseline: 1.0028x; 1.0007x over previous
#include <cuda_runtime.h>

// QHadamard: y = FWHT_4096(x) / 64, rows = 8192, DIM = 4096.
// R17 = R16 body (padded smem; ALU-free addressing; regs=48 natural) with
// __launch_bounds__(128, 10): the 10-block register budget (51) exceeds the
// natural 48, so two extra resident blocks (40 warps/SM) come at zero spill
// cost. Layout: phys(a) = a + 4*(a>>7) (4 pad words / 128-word segment).
// Bit assignment (element e[11:0]):
//   A: transforms {0,1,7,8,9}: 8x LDG.128 (c=e{0,1}, r=e{7,8,9}, lane=e{2..6},
//      warp=e{10,11}), 8x STS.128 at baseA + 132r words.
//   B: transforms {2..6}: scalar smem in-place at baseB + 4m words.
//   C: transforms {10,11}: 8x LDS.128 at baseC + 528r words; 8x STG.128 dense.
// All phases bank-conflict-free (T1/C: words 4*lane+const; B: bank =
// (l&3)+4*((m+(l>>2))&7) -> 32 distinct). A->B intra-warp -> __syncwarp.

#define DIM 4096
#define THREADS 128
#define SPAD 4224                              // 4096 + 4*32 pad words

__device__ __forceinline__ void bfly(float& a, float& b) {
    float t = a; a = t + b; b = t - b;
}

__device__ __forceinline__ void fwht32(float* x) {
#pragma unroll
    for (int h = 1; h < 32; h <<= 1)
#pragma unroll
        for (int i = 0; i < 32; i += (h << 1))
#pragma unroll
            for (int j = i; j < i + h; ++j) bfly(x[j], x[j + h]);
}

__global__ void __launch_bounds__(THREADS, 10)
QHadamard_24524263260380_kernel(const float* __restrict__ in,
                                float* __restrict__ out) {
    __shared__ float s[SPAD];                   // 16.5 KB, padded layout

    const int    T   = threadIdx.x;             // 0..127
    const size_t row = (size_t)blockIdx.x * DIM;
    const int    L   = T & 31;                  // e{2..6}
    const int    W   = T >> 5;                  // e{10,11}

    // ---- Pass A: 8x LDG.128; x[r*4+c]: c=e{0,1}, r=e{7,8,9} ----
    const float4* g4 = reinterpret_cast<const float4*>(in + row);
    const int qa = L + (W << 8);                // f4 index base; + r*32
    float x[32];
#pragma unroll
    for (int r = 0; r < 8; ++r) {
        float4 v = g4[qa + (r << 5)];
        x[r*4+0] = v.x; x[r*4+1] = v.y; x[r*4+2] = v.z; x[r*4+3] = v.w;
    }
    const float scale = 0.015625f;              // 1/sqrt(4096)
#pragma unroll
    for (int k = 0; k < 32; ++k) x[k] *= scale;

    fwht32(x);                                  // FWHT over e{0,1,7,8,9}

    // ---- T1: 8x STS.128 at word baseA + 132r  (baseA = 4L + 1056W) ----
    {
        float* sA = s + (L << 2) + W * 1056;
#pragma unroll
        for (int r = 0; r < 8; ++r) {
            *reinterpret_cast<float4*>(sA + r * 132) =
                make_float4(x[r*4+0], x[r*4+1], x[r*4+2], x[r*4+3]);
        }
    }
    // A->B exchange is intra-warp: warp-local sync suffices.
    __syncwarp(0xffffffffu);

    // ---- Pass B: scalar in-place; thread owns e{0,1}=T&3, e{7..11}=T>>2;
    //      m = e{2..6}; word = baseB + 4m  (baseB = (T&3) + 132*(T>>2)) ----
    {
        float* sB = s + (T & 3) + (T >> 2) * 132;
        float y[32];
#pragma unroll
        for (int m = 0; m < 32; ++m) y[m] = sB[m << 2];

        fwht32(y);                              // FWHT over e{2..6}

#pragma unroll
        for (int m = 0; m < 32; ++m) sB[m << 2] = y[m];
    }
    __syncthreads();                            // B->C spans all warps

    // ---- Pass C: lane=e{2..6}=T&31, w=e{7,8}=T>>5, r=e{9,10,11};
    //      word = baseC + 528r  (baseC = 4T + 4w) ----
    float z[32];
    {
        const float* sC = s + (T << 2) + ((T >> 5) << 2);
#pragma unroll
        for (int r = 0; r < 8; ++r) {
            float4 v = *reinterpret_cast<const float4*>(sC + r * 528);
            z[r*4+0] = v.x; z[r*4+1] = v.y; z[r*4+2] = v.z; z[r*4+3] = v.w;
        }
    }
    // FWHT over e{10,11} = z-index bits {3,4}
#pragma unroll
    for (int hi = 0; hi < 32; hi += 16)
#pragma unroll
        for (int j = 0; j < 8; ++j) bfly(z[hi + j], z[hi + j + 8]);
#pragma unroll
    for (int j = 0; j < 16; ++j) bfly(z[j], z[j + 16]);

    // ---- 8x STG.128, dense: per instruction 32 consecutive float4 ----
    float4* o4 = reinterpret_cast<float4*>(out + row);
#pragma unroll
    for (int r = 0; r < 8; ++r) {
        o4[T + (r << 7)] =
            make_float4(z[r*4+0], z[r*4+1], z[r*4+2], z[r*4+3]);
    }
}

extern "C" void kernel_launch(void* const* d_in, const int* in_sizes, int n_in,
                              void* d_out, int out_size) {
    const float* x   = (const float*)d_in[0];
    float*       out = (float*)d_out;
    const int rows = in_sizes[0] / DIM;          // 8192
    QHadamard_24524263260380_kernel<<<rows, THREADS>>>(x, out);
}